// round 17
// baseline (speedup 1.0000x reference)
#include <cuda_runtime.h>
#include <cuda_bf16.h>
#include <cstdint>

// ---------------- device scratch (globals — allowed) ----------------
__device__ __nv_bfloat16 g_Ebf[98304UL * 1024];   // E in bf16, row-major
__device__ __nv_bfloat16 g_Wt[8 * 256 * 1024];    // [head][n (Q0..127|K128..255)][k]
__device__ float         g_gate[16384 * 6];

namespace {

constexpr int  kSamples = 16384;
constexpr long kRows    = 98304;               // 16384*6
constexpr int  CHUNKS   = 32;                  // K=1024 / 32
constexpr int  SPC      = 10;                  // samples per CTA tile (60 rows, pad 64)
constexpr int  MTILES   = (kSamples + SPC - 1) / SPC;  // 1639
constexpr int  STAGE    = 20480;               // A 4KB + B 16KB
constexpr int  BOFF     = 4096;                // B within stage
constexpr int  QKS2     = 258;                 // qk stride (bf16); qk aliases stages
constexpr uint32_t BIASO = 61440;              // after 3 stages
constexpr uint32_t SCO   = 62464;              // bias 256 f32
constexpr int  SMEM_TOTAL = 64512;             // 2 CTAs/SM (RF-capped anyway)

__device__ __forceinline__ uint32_t smem_u32(const void* p) {
  return (uint32_t)__cvta_generic_to_shared(p);
}
__device__ __forceinline__ void cpa16(uint32_t dst, const void* src, int sz) {
  asm volatile("cp.async.cg.shared.global [%0], [%1], 16, %2;\n"
               :: "r"(dst), "l"(src), "r"(sz));
}
__device__ __forceinline__ void ldsm4(uint32_t* r, uint32_t addr) {
  asm volatile("ldmatrix.sync.aligned.m8n8.x4.shared.b16 {%0,%1,%2,%3}, [%4];"
               : "=r"(r[0]), "=r"(r[1]), "=r"(r[2]), "=r"(r[3]) : "r"(addr));
}
__device__ __forceinline__ void mma_bf16(float* d, const uint32_t* a, const uint32_t* b) {
  asm volatile(
      "mma.sync.aligned.m16n8k16.row.col.f32.bf16.bf16.f32 "
      "{%0,%1,%2,%3}, {%4,%5,%6,%7}, {%8,%9}, {%0,%1,%2,%3};\n"
      : "+f"(d[0]), "+f"(d[1]), "+f"(d[2]), "+f"(d[3])
      : "r"(a[0]), "r"(a[1]), "r"(a[2]), "r"(a[3]), "r"(b[0]), "r"(b[1]));
}

}  // namespace

// ---------------- merged pre-pass kernel ----------------
__global__ void prep_kernel(const float* __restrict__ emb,
                            const float* __restrict__ Wq, const float* __restrict__ Wk,
                            const float* __restrict__ ac, const float* __restrict__ Wg,
                            const float* __restrict__ bg) {
  const int b = blockIdx.x;
  const int tid = threadIdx.x;
  if (b < 8192) {
    // E -> bf16
    const long total = kRows * 1024 / 8;
    for (long i = b * 256L + tid; i < total; i += 8192L * 256) {
      const float4* s = (const float4*)emb + i * 2;
      float4 a = s[0], bb = s[1];
      __nv_bfloat162* o = (__nv_bfloat162*)g_Ebf + i * 4;
      o[0] = __floats2bfloat162_rn(a.x, a.y);
      o[1] = __floats2bfloat162_rn(a.z, a.w);
      o[2] = __floats2bfloat162_rn(bb.x, bb.y);
      o[3] = __floats2bfloat162_rn(bb.z, bb.w);
    }
  } else if (b < 8192 + 1024) {
    // W -> K-major bf16
    const int idx = (b - 8192) * 256 + tid;  // 262144
    const int h  = idx >> 15;
    const int n  = (idx >> 7) & 255;
    const int k0 = (idx & 127) * 8;
    const float* W = (n < 128) ? Wq : Wk;
    const int col = h * 128 + (n & 127);
    __nv_bfloat16* o = g_Wt + ((long)(h * 256 + n)) * 1024 + k0;
#pragma unroll
    for (int t = 0; t < 8; t++) o[t] = __float2bfloat16(W[(long)(k0 + t) * 1024 + col]);
  } else {
    // gates
    const int idx = (b - 9216) * 256 + tid;  // 98304
    const int s = idx / 6, j = idx % 6;
    const float* ap = ac + (long)s * 128;
    float g = bg[j];
#pragma unroll 8
    for (int c = 0; c < 128; c++) g = fmaf(ap[c], Wg[c * 6 + j], g);
    g_gate[idx] = g;
  }
}

// ------- main fused kernel: one (mtile, head) per CTA, 2 CTAs/SM, 3-stage -------
__global__ void __launch_bounds__(256, 2)
attn_main_kernel(const float* __restrict__ emb, const float* __restrict__ bk,
                 const float* __restrict__ bq, float* __restrict__ ctx,
                 float* __restrict__ att) {
  extern __shared__ char smc[];
  const uint32_t sb = smem_u32(smc);
  __nv_bfloat16* qkb = (__nv_bfloat16*)smc;   // 64 x 258 bf16, aliases stages post-GEMM
  float* bia = (float*)(smc + BIASO);
  float* sc  = (float*)(smc + SCO);

  const int tid  = threadIdx.x;
  const int lane = tid & 31;
  const int warp = tid >> 5;
  const int mw   = warp >> 2;   // 0..1 (32-row band)
  const int nw   = warp & 3;    // 0..3 (64-col band)
  const int lr   = lane >> 2;   // 0..7
  const int lc   = lane & 3;    // 0..3

  const int head  = blockIdx.x & 7;
  const int mtile = blockIdx.x >> 3;
  const int sbase = mtile * SPC;

  // hoisted byte-base pointers (32-bit per-op offsets)
  const char* ab = (const char*)g_Ebf + (uint32_t)(sbase * 6) * 2048u;
  const char* wb = (const char*)g_Wt + (size_t)head * 524288u;

  bia[tid] = (tid < 128) ? bq[head * 128 + tid] : bk[head * 128 + tid - 128];

  // ---- ldmatrix address precompute (packed-row layout: 2 logical 64B rows / 128B phys)
  const int gq = lane >> 3, li = lane & 7;
  const uint32_t xr = (uint32_t)(li << 4);                 // swizzle XOR (both A and B)
  const uint32_t aOff0 = (uint32_t)(((gq & 1) * 8 + li) * 128);      // mt=0
  const uint32_t aOff1 = aOff0 + 2048;                                // mt=1 (+16 rows)
  const uint32_t bP0   = (uint32_t)((nw & 1) * 64 + (gq >> 1) * 8 + li) * 128 + BOFF;
  // unit-index bases (x16 bytes): A: mw*4 + ks*2 + (gq>>1); B: (nw>>1)*4 + ks*2 + (gq&1)
  const uint32_t uA0 = (uint32_t)((mw * 4 + (gq >> 1)) * 16);         // + ks*32
  const uint32_t uB0 = (uint32_t)(((nw >> 1) * 4 + (gq & 1)) * 16);   // + ks*32

  auto loadA = [&](int c, int stage) {
    const uint32_t kb = (uint32_t)(c * 64);   // 32 k * 2B
    const int r = tid >> 2, ch = tid & 3;     // 64 rows x 4 units
    const bool ok = (r < 60) && ((long)(sbase * 6 + r) < kRows);
    const int p = r & 31, hi = r >> 5;
    const uint32_t dst = sb + stage * STAGE + (uint32_t)(p * 128) +
                         (uint32_t)(((hi * 4 + ch) * 16) ^ ((p & 7) << 4));
    const uint32_t soff = ok ? (uint32_t)(r * 2048 + ch * 16) : 0u;
    cpa16(dst, ab + soff + kb, ok ? 16 : 0);
  };
  auto loadB = [&](int c, int stage) {
    const uint32_t kb = (uint32_t)(c * 64);
#pragma unroll
    for (int it = 0; it < 4; it++) {
      const int v = tid + it * 256;           // 0..1023
      const int n = v >> 2, ch = v & 3;       // 256 rows x 4 units
      const int p = n & 127, hi = n >> 7;
      const uint32_t dst = sb + stage * STAGE + BOFF + (uint32_t)(p * 128) +
                           (uint32_t)(((hi * 4 + ch) * 16) ^ ((p & 7) << 4));
      cpa16(dst, wb + (uint32_t)(n * 2048 + ch * 16) + kb, 16);
    }
  };

  float acc[2][8][4];
#pragma unroll
  for (int a0 = 0; a0 < 2; a0++)
#pragma unroll
    for (int a1 = 0; a1 < 8; a1++)
#pragma unroll
      for (int a2 = 0; a2 < 4; a2++) acc[a0][a1][a2] = 0.f;

  loadA(0, 0); loadB(0, 0);
  asm volatile("cp.async.commit_group;" ::: "memory");
  loadA(1, 1); loadB(1, 1);
  asm volatile("cp.async.commit_group;" ::: "memory");

  uint32_t aF[2][2][4];   // [ks parity][m tile][4]
  uint32_t bF[2][4];      // [nt parity][4]

  for (int c = 0; c < CHUNKS; c++) {
    if (c < CHUNKS - 1) asm volatile("cp.async.wait_group 1;" ::: "memory");
    else                asm volatile("cp.async.wait_group 0;" ::: "memory");
    __syncthreads();      // single sync: also proves stage (c+2)%3 is free

    if (c + 2 < CHUNKS) {
      loadA(c + 2, (c + 2) % 3);
      loadB(c + 2, (c + 2) % 3);
      asm volatile("cp.async.commit_group;" ::: "memory");
    }

    const uint32_t stb = sb + (uint32_t)((c % 3) * STAGE);

    // prologue fragments for ks=0, nt=0
    ldsm4(aF[0][0], stb + aOff0 + (uA0 ^ xr));
    ldsm4(aF[0][1], stb + aOff1 + (uA0 ^ xr));
    ldsm4(bF[0],    stb + bP0   + (uB0 ^ xr));

#pragma unroll
    for (int ks = 0; ks < 2; ks++) {
      const int kcur = ks, knxt = ks ^ 1;
#pragma unroll
      for (int nt = 0; nt < 4; nt++) {
        const int cur = nt & 1, nxt = cur ^ 1;
        if (nt < 3) {
          ldsm4(bF[nxt], stb + bP0 + (uint32_t)((nt + 1) * 2048) +
                         ((uB0 + (uint32_t)(ks * 32)) ^ xr));
        } else if (ks < 1) {
          const uint32_t ua = uA0 + 32, ub = uB0 + 32;
          ldsm4(aF[knxt][0], stb + aOff0 + (ua ^ xr));
          ldsm4(aF[knxt][1], stb + aOff1 + (ua ^ xr));
          ldsm4(bF[nxt],     stb + bP0   + (ub ^ xr));
        }
        mma_bf16(acc[0][nt * 2],     aF[kcur][0], bF[cur]);
        mma_bf16(acc[0][nt * 2 + 1], aF[kcur][0], bF[cur] + 2);
        mma_bf16(acc[1][nt * 2],     aF[kcur][1], bF[cur]);
        mma_bf16(acc[1][nt * 2 + 1], aF[kcur][1], bF[cur] + 2);
      }
    }
  }
  __syncthreads();   // all mma done; stage area reusable as qk

  // ---- dump Q|K tile (+bias) into bf16 qk region
#pragma unroll
  for (int mt = 0; mt < 2; mt++)
#pragma unroll
    for (int nt = 0; nt < 8; nt++) {
      const int r0 = mw * 32 + mt * 16 + lr;     // <= 55
      const int c0 = nw * 64 + nt * 8 + 2 * lc;
      *(__nv_bfloat162*)&qkb[r0 * QKS2 + c0] =
          __floats2bfloat162_rn(acc[mt][nt][0] + bia[c0], acc[mt][nt][1] + bia[c0 + 1]);
      *(__nv_bfloat162*)&qkb[(r0 + 8) * QKS2 + c0] =
          __floats2bfloat162_rn(acc[mt][nt][2] + bia[c0], acc[mt][nt][3] + bia[c0 + 1]);
    }
  __syncthreads();

  const float kInvSqrt = 0.08838834764831845f;  // 1/sqrt(128)

  // ---- scores: one warp per sample
  for (int s = warp; s < SPC; s += 8) {
    const int sg = sbase + s;
    if (sg >= kSamples) continue;
    float qv[6][4], kv[6][4];
#pragma unroll
    for (int i = 0; i < 6; i++) {
      const __nv_bfloat16* qp = qkb + (s * 6 + i) * QKS2 + lane;
#pragma unroll
      for (int u = 0; u < 4; u++) {
        qv[i][u] = __bfloat162float(qp[32 * u]);
        kv[i][u] = __bfloat162float(qp[128 + 32 * u]);
      }
    }
#pragma unroll
    for (int i = 0; i < 6; i++)
#pragma unroll
      for (int j = 0; j < 6; j++) {
        float p = qv[i][0] * kv[j][0] + qv[i][1] * kv[j][1]
                + qv[i][2] * kv[j][2] + qv[i][3] * kv[j][3];
#pragma unroll
        for (int o = 16; o > 0; o >>= 1) p += __shfl_xor_sync(0xffffffffu, p, o);
        if (lane == 0) sc[s * 36 + i * 6 + j] = p;
      }
  }
  __syncthreads();

  // ---- gated softmax; write attention; keep A in smem
  if (tid < SPC * 6) {
    const int s = tid / 6, i = tid % 6;
    const int sg = sbase + s;
    if (sg < kSamples) {
      float l[6], mx = -1e30f;
#pragma unroll
      for (int j = 0; j < 6; j++) {
        l[j] = sc[s * 36 + i * 6 + j] * kInvSqrt * g_gate[sg * 6 + j];
        mx = fmaxf(mx, l[j]);
      }
      float sum = 0.f;
#pragma unroll
      for (int j = 0; j < 6; j++) { l[j] = expf(l[j] - mx); sum += l[j]; }
      const float rcp = 1.f / sum;
      float* ao = att + (((long)sg * 8 + head) * 6 + i) * 6;
#pragma unroll
      for (int j = 0; j < 6; j++) {
        const float a = l[j] * rcp;
        ao[j] = a;
        sc[s * 36 + i * 6 + j] = a;
      }
    }
  }
  __syncthreads();

  // ---- context: ctx[6s+i, head*128+cc] = sum_j A[i][j] * E[6s+j, head*128+cc]
  for (int idx = tid; idx < SPC * 128; idx += 256) {
    const int s = idx >> 7;
    const int cc = idx & 127;
    const int sg = sbase + s;
    if (sg >= kSamples) continue;
    const float* ep = emb + (long)sg * 6 * 1024 + head * 128 + cc;
    float e[6];
#pragma unroll
    for (int j = 0; j < 6; j++) e[j] = ep[(long)j * 1024];
#pragma unroll
    for (int i = 0; i < 6; i++) {
      float v = 0.f;
#pragma unroll
      for (int j = 0; j < 6; j++) v = fmaf(sc[s * 36 + i * 6 + j], e[j], v);
      ctx[((long)sg * 6 + i) * 1024 + head * 128 + cc] = v;
    }
  }
}

extern "C" void kernel_launch(void* const* d_in, const int* in_sizes, int n_in,
                              void* d_out, int out_size) {
  (void)in_sizes; (void)n_in; (void)out_size;
  const float* emb = (const float*)d_in[0];
  const float* ac  = (const float*)d_in[1];
  const float* Wk  = (const float*)d_in[2];
  const float* bk  = (const float*)d_in[3];
  const float* Wq  = (const float*)d_in[4];
  const float* bq  = (const float*)d_in[5];
  const float* Wg  = (const float*)d_in[6];
  const float* bg  = (const float*)d_in[7];

  float* ctx = (float*)d_out;
  float* att = ctx + kRows * 1024L;

  prep_kernel<<<9600, 256>>>(emb, Wq, Wk, ac, Wg, bg);

  cudaFuncSetAttribute(attn_main_kernel,
                       cudaFuncAttributeMaxDynamicSharedMemorySize, SMEM_TOTAL);
  attn_main_kernel<<<MTILES * 8, 256, SMEM_TOTAL>>>(emb, bk, bq, ctx, att);
}